// round 14
// baseline (speedup 1.0000x reference)
#include <cuda_runtime.h>
#include <cuda_fp16.h>

#define B_   128
#define S_   512
#define D_   256
#define H_   512
#define ODIM 1275
#define NCTA 64

typedef unsigned long long u64;
typedef unsigned int u32;

// ---------------- persistent device scratch (pre-swizzled f16 tiles) ----------
// act tile = [128 rows][128 k] f16, 256B rows; 16B chunk c of row r at pos c^(r&7).
__device__ __align__(256) unsigned char g_xs[S_][2][32768];    // x: [t][ch]
__device__ __align__(256) unsigned char g_h0s[2][4][32768];    // h0: [buf][ch]
__device__ __align__(256) unsigned char g_h1s[2][4][32768];
// weight tiles: [cta] (pair = cta>>1, half = cta&1), 64 rows x 128 k = 16KB
__device__ __align__(256) unsigned char g_W0s[NCTA][3][16384];
__device__ __align__(256) unsigned char g_W1s[NCTA][4][16384];
// pairwise partial-z exchange: [cta][phase][warpslot][lane][32 f32]
__device__ __align__(16) float g_zex[NCTA][2][4][32][32];
__device__ unsigned g_flags[NCTA * 32];   // [cta*32+0]=barrier, [cta*32+16]=exchange

// ---------------- helpers ----------------
__device__ __forceinline__ u32 smem_u32(const void* p) {
    u32 a; asm("{ .reg .u64 t; cvta.to.shared.u64 t, %1; cvt.u32.u64 %0, t; }" : "=r"(a) : "l"(p));
    return a;
}
__device__ __forceinline__ float ex2f(float x) { float y; asm("ex2.approx.ftz.f32 %0, %1;" : "=f"(y) : "f"(x)); return y; }
__device__ __forceinline__ float rcpf(float x) { float y; asm("rcp.approx.ftz.f32 %0, %1;" : "=f"(y) : "f"(x)); return y; }
__device__ __forceinline__ float fsig(float z)  { return rcpf(1.f + ex2f(-1.44269504088896f * z)); }
__device__ __forceinline__ float ftanh(float z) { return 1.f - 2.f * rcpf(1.f + ex2f(2.88539008177793f * z)); }

__device__ __forceinline__ void cp16(void* dst, const void* src) {
    u32 d = smem_u32(dst);
    asm volatile("cp.async.cg.shared.global [%0], [%1], 16;\n" :: "r"(d), "l"(src));
}
__device__ __forceinline__ void cp_commit() { asm volatile("cp.async.commit_group;\n" ::); }
#define CP_WAIT0() asm volatile("cp.async.wait_group 0;\n" ::)
#define CP_WAIT1() asm volatile("cp.async.wait_group 1;\n" ::)

#define LDM4(r0, r1, r2, r3, addr) \
    asm volatile("ldmatrix.sync.aligned.m8n8.x4.shared.b16 {%0,%1,%2,%3}, [%4];" \
        : "=r"(r0), "=r"(r1), "=r"(r2), "=r"(r3) : "r"(addr))

#define MMA4(d, A0, A1, A2, A3, B0, B1) \
    asm volatile("mma.sync.aligned.m16n8k16.row.col.f32.f16.f16.f32 " \
        "{%0,%1,%2,%3}, {%4,%5,%6,%7}, {%8,%9}, {%0,%1,%2,%3};" \
        : "+f"((d)[0]), "+f"((d)[1]), "+f"((d)[2]), "+f"((d)[3]) \
        : "r"(A0), "r"(A1), "r"(A2), "r"(A3), "r"(B0), "r"(B1))

// ---------------- grid-wide barrier (per-CTA flag slots) ----------------
__device__ __forceinline__ void grid_sync_flag(int jt, int tid, unsigned gen) {
    __syncthreads();
    if (tid == 0) {
        __threadfence();
        *((volatile unsigned*)&g_flags[jt * 32]) = gen;
    }
    if (tid < NCTA) {
        while (*((volatile unsigned*)&g_flags[tid * 32]) < gen) { }
    }
    __threadfence();
    __syncthreads();
}

// swizzled element offset inside a [rows][128k] f16 tile
__device__ __forceinline__ u32 swzoff(int row, int k) {
    return (u32)row * 256u + ((((u32)(k >> 3)) ^ ((u32)row & 7u)) << 4) + (((u32)k & 7u) << 1);
}

// ---------------- prep: f16-convert + swizzle x, W; zero h; reset flags -------
__global__ void prep_kernel(const float* __restrict__ x,
                            const float* __restrict__ W0,
                            const float* __restrict__ W1)
{
    const int stride = gridDim.x * blockDim.x;
    const int t0 = blockIdx.x * blockDim.x + threadIdx.x;

    if (t0 < NCTA * 32) g_flags[t0] = 0u;

    for (int i = t0; i < 2 * 4 * 32768 / 4; i += stride) {
        ((u32*)g_h0s)[i] = 0u;
        ((u32*)g_h1s)[i] = 0u;
    }
    for (int idx = t0; idx < S_ * 2 * 128 * 128; idx += stride) {
        int t   = idx / (2 * 128 * 128);
        int rem = idx % (2 * 128 * 128);
        int ch  = rem / (128 * 128);
        int b   = (rem / 128) % 128;
        int k   = rem % 128;
        float v = x[(b * S_ + t) * D_ + ch * 128 + k];
        *(__half*)(&g_xs[t][ch][swzoff(b, k)]) = __float2half_rn(v);
    }
    // W0: cta = pair*2+half; rows n = gate*16+ui -> col gate*512 + pair*16 + ui;
    // global k = half*384 + ch*128 + kk
    for (int idx = t0; idx < NCTA * 3 * 64 * 128; idx += stride) {
        int cta = idx / (3 * 64 * 128);
        int rem = idx % (3 * 64 * 128);
        int ch  = rem / (64 * 128);
        int n   = (rem / 128) % 64;
        int kk  = rem % 128;
        int gk  = (cta & 1) * 384 + ch * 128 + kk;
        float v = W0[gk * 2048 + (n >> 4) * 512 + (cta >> 1) * 16 + (n & 15)];
        *(__half*)(&g_W0s[cta][ch][swzoff(n, kk)]) = __float2half_rn(v);
    }
    // W1: global k = half*512 + ch*128 + kk
    for (int idx = t0; idx < NCTA * 4 * 64 * 128; idx += stride) {
        int cta = idx / (4 * 64 * 128);
        int rem = idx % (4 * 64 * 128);
        int ch  = rem / (64 * 128);
        int n   = (rem / 128) % 64;
        int kk  = rem % 128;
        int gk  = (cta & 1) * 512 + ch * 128 + kk;
        float v = W1[gk * 2048 + (n >> 4) * 512 + (cta >> 1) * 16 + (n & 15)];
        *(__half*)(&g_W1s[cta][ch][swzoff(n, kk)]) = __float2half_rn(v);
    }
}

// ---------------- linear 32KB stage (src pre-swizzled in gmem) ----------------
__device__ __forceinline__ void stage(unsigned char* dst, const unsigned char* src, int tid) {
    #pragma unroll
    for (int i = 0; i < 8; i++) {
        int o = (tid + (i << 8)) << 4;
        cp16(dst + o, src + o);
    }
}

// ---------------- per-lane ldmatrix/mma context ----------------
struct LaneCtx { u32 sA, rA, kgA, rB, kgB; };

// one K=128 chunk of D[M=64 cols][N=128 b]; per-warp m64 x n16.
// acc[mt*8 + nt*4 + s*2 + e]: mt = gate, s = unit-sel (l8 / l8+8), e = batch elem.
__device__ __forceinline__ void mma_chunk(u32 ab, u32 wb, float* acc, const LaneCtx& L) {
    const u32 aB = wb + L.rA * 256u;
    const u32 bB = ab + L.rB * 256u;
    #pragma unroll
    for (int j = 0; j < 8; j++) {
        u32 kiA = ((((u32)(2 * j)) | L.kgA) ^ L.sA) << 4;
        u32 kiB = ((((u32)(2 * j)) | L.kgB) ^ L.sA) << 4;
        u32 b0, b1, b2, b3;
        LDM4(b0, b1, b2, b3, bB + kiB);
        #pragma unroll
        for (int mt = 0; mt < 4; mt++) {
            u32 a0, a1, a2, a3;
            LDM4(a0, a1, a2, a3, aB + (u32)mt * 4096u + kiA);
            MMA4(acc + mt * 8 + 0, a0, a1, a2, a3, b0, b1);
            MMA4(acc + mt * 8 + 4, a0, a1, a2, a3, b2, b3);
        }
    }
}

// ---------------- K-half GEMM phase: depth-2 staged ring over nq chunks --------
__device__ __forceinline__ void kphase(
    const unsigned char* q0, const unsigned char* q1,
    const unsigned char* q2, const unsigned char* q3, int nq,
    u32 wb, unsigned char* s_act, u32 actbase,
    float* acc, int tid, const LaneCtx& L)
{
    const unsigned char* q[4] = {q0, q1, q2, q3};
    #pragma unroll
    for (int i = 0; i < 32; i++) acc[i] = 0.f;

    stage(s_act, q[0], tid); cp_commit();
    if (nq > 1) { stage(s_act + 32768, q[1], tid); cp_commit(); }

    int buf = 0;
    for (int g = 0; g < nq; g++) {
        if (g < nq - 1) { CP_WAIT1(); } else { CP_WAIT0(); }
        __syncthreads();
        if (g + 2 < nq) {
            int nb = buf + 2; if (nb >= 3) nb -= 3;
            stage(s_act + nb * 32768, q[g + 2], tid);
            cp_commit();
        }
        mma_chunk(actbase + (u32)buf * 32768u, wb + ((u32)g << 14), acc, L);
        if (++buf == 3) buf = 0;
    }
    __syncthreads();
}

// ---------------- pair exchange + epilogue ----------------
// half0: warps 0-3 do gates (batches 0-63), warps 4-7 export; half1 mirrored.
__device__ __forceinline__ void exchange_epilogue(
    float* acc, float* cst, const float* bias8,
    unsigned char* hdst, int pair, int half, int jt,
    int warp, int lane, int tid, u32 egen, int phase)
{
    const bool exporter = (half == 0) ? (warp >= 4) : (warp < 4);
    float4* ex = (float4*)&g_zex[jt][phase][warp & 3][lane][0];
    if (exporter) {
        #pragma unroll
        for (int i = 0; i < 8; i++)
            ex[i] = make_float4(acc[4 * i], acc[4 * i + 1], acc[4 * i + 2], acc[4 * i + 3]);
    }
    __threadfence();
    __syncthreads();
    if (tid == 0) *((volatile u32*)&g_flags[jt * 32 + 16]) = egen;
    {
        volatile u32* pf = (volatile u32*)&g_flags[(jt ^ 1) * 32 + 16];
        while (*pf < egen) { }
    }
    __threadfence();

    if (!exporter) {
        const float4* im = (const float4*)&g_zex[jt ^ 1][phase][warp & 3][lane][0];
        #pragma unroll
        for (int i = 0; i < 8; i++) {
            float4 v = im[i];
            acc[4 * i] += v.x; acc[4 * i + 1] += v.y; acc[4 * i + 2] += v.z; acc[4 * i + 3] += v.w;
        }
        const int l8 = (lane >> 2);
        #pragma unroll
        for (int s = 0; s < 2; s++) {
            const int jcol = (pair * 16 + l8 + 8 * s) & 127;
            #pragma unroll
            for (int nt = 0; nt < 2; nt++) {
                #pragma unroll
                for (int e = 0; e < 2; e++) {
                    float zi = acc[0 * 8 + nt * 4 + s * 2 + e] + bias8[s * 4 + 0];
                    float zf = acc[1 * 8 + nt * 4 + s * 2 + e] + bias8[s * 4 + 1];
                    float zg = acc[2 * 8 + nt * 4 + s * 2 + e] + bias8[s * 4 + 2];
                    float zo = acc[3 * 8 + nt * 4 + s * 2 + e] + bias8[s * 4 + 3];
                    float c  = cst[s * 4 + nt * 2 + e];
                    float cn = fsig(zf) * c + fsig(zi) * ftanh(zg);
                    cst[s * 4 + nt * 2 + e] = cn;
                    float h = fsig(zo) * ftanh(cn);
                    int b = warp * 16 + nt * 8 + (lane & 3) * 2 + e;
                    *(__half*)(hdst + swzoff(b, jcol)) = __float2half_rn(h);
                }
            }
        }
    }
    __syncthreads();
}

// ---------------- persistent main kernel: 64 CTAs x 256 threads ----------------
__global__ void __launch_bounds__(256, 1)
lstm_main(const float* __restrict__ b0g,
          const float* __restrict__ b1g,
          const float* __restrict__ Wp,
          const float* __restrict__ bp,
          float* __restrict__ out)
{
    extern __shared__ __align__(256) unsigned char smem[];
    unsigned char* s_w0  = smem;              // 3 x 16384 = 49152
    unsigned char* s_w1  = smem + 49152;      // 4 x 16384 = 65536
    unsigned char* s_act = smem + 114688;     // 3 x 32768 = 98304 -> total 212992

    const int tid  = threadIdx.x;
    const int lane = tid & 31;
    const int warp = tid >> 5;
    const int jt   = blockIdx.x;
    const int pair = jt >> 1;
    const int half = jt & 1;

    // preload this CTA's K-half weights (48KB + 64KB), linear cp.async
    {
        const unsigned char* w0 = &g_W0s[jt][0][0];
        const unsigned char* w1 = &g_W1s[jt][0][0];
        #pragma unroll
        for (int i = 0; i < 12; i++) { int o = (tid + (i << 8)) << 4; cp16(s_w0 + o, w0 + o); }
        #pragma unroll
        for (int i = 0; i < 16; i++) { int o = (tid + (i << 8)) << 4; cp16(s_w1 + o, w1 + o); }
        cp_commit();
        CP_WAIT0();
    }
    __syncthreads();

    // per-lane biases: units {l8, l8+8} of this pair, gates i,f,g,o
    float bias0[8], bias1[8];
    {
        const int l8 = lane >> 2;
        #pragma unroll
        for (int s = 0; s < 2; s++) {
            int j = pair * 16 + l8 + 8 * s;
            #pragma unroll
            for (int g = 0; g < 4; g++) {
                bias0[s * 4 + g] = b0g[g * 512 + j];
                bias1[s * 4 + g] = b1g[g * 512 + j];
            }
        }
    }

    float c0r[8] = {0,0,0,0,0,0,0,0};
    float c1r[8] = {0,0,0,0,0,0,0,0};
    float acc[32];

    const u32 actbase = smem_u32(s_act);
    const u32 wb0 = smem_u32(s_w0);
    const u32 wb1 = smem_u32(s_w1);
    const int htile = pair >> 3;

    LaneCtx L;
    L.sA  = (u32)(lane & 7);
    L.rA  = (u32)((((lane >> 3) & 1) << 3) | (lane & 7));
    L.kgA = (u32)(lane >> 4);
    L.rB  = (u32)(((lane >> 4) << 3) + (lane & 7) + warp * 16);
    L.kgB = (u32)((lane >> 3) & 1);

    for (int t = 0; t < S_; t++) {
        const int cur = t & 1, prv = cur ^ 1;

        // ---- L0(t): half0 K = [x ch0, x ch1, h0prev t0]; half1 = [h0prev t1,t2,t3]
        if (half == 0)
            kphase(&g_xs[t][0][0], &g_xs[t][1][0], &g_h0s[prv][0][0], 0, 3,
                   wb0, s_act, actbase, acc, tid, L);
        else
            kphase(&g_h0s[prv][1][0], &g_h0s[prv][2][0], &g_h0s[prv][3][0], 0, 3,
                   wb0, s_act, actbase, acc, tid, L);
        exchange_epilogue(acc, c0r, bias0, &g_h0s[cur][htile][0],
                          pair, half, jt, warp, lane, tid, (u32)(2 * t + 1), 0);

        grid_sync_flag(jt, tid, (unsigned)(t + 1));   // h0(t), h1(t-1) final everywhere

        // ---- L1(t): half0 K = h0cur t0-3; half1 = h1prev t0-3
        if (half == 0)
            kphase(&g_h0s[cur][0][0], &g_h0s[cur][1][0], &g_h0s[cur][2][0], &g_h0s[cur][3][0], 4,
                   wb1, s_act, actbase, acc, tid, L);
        else
            kphase(&g_h1s[prv][0][0], &g_h1s[prv][1][0], &g_h1s[prv][2][0], &g_h1s[prv][3][0], 4,
                   wb1, s_act, actbase, acc, tid, L);
        exchange_epilogue(acc, c1r, bias1, &g_h1s[cur][htile][0],
                          pair, half, jt, warp, lane, tid, (u32)(2 * t + 2), 1);
        // next step's grid_sync orders h1(t) -> L1(t+1)
    }

    grid_sync_flag(jt, tid, (unsigned)(S_ + 1));

    // ---- projection: out[b][m] = sum_j h1[b][j] * Wp[j][m] + bp[m] ----
    {
        const unsigned char* h1b = &g_h1s[1][0][0];   // buf 1 (t = 511)
        int mstart = jt * 20;
        int mend = mstart + 20; if (mend > ODIM) mend = ODIM;
        int b  = tid & 127;
        int mq = tid >> 7;     // 0..1
        for (int m = mstart + mq; m < mend; m += 2) {
            float a = bp[m];
            for (int k = 0; k < H_; k++) {
                u32 off = swzoff(b, k & 127);
                a += __half2float(*(const __half*)(h1b + (size_t)(k >> 7) * 32768 + off))
                     * Wp[k * ODIM + m];
            }
            out[b * ODIM + m] = a;
        }
    }
}

// ---------------- entry ----------------
extern "C" void kernel_launch(void* const* d_in, const int* in_sizes, int n_in,
                              void* d_out, int out_size)
{
    const float* x  = (const float*)d_in[0];
    const float* W0 = (const float*)d_in[1];
    const float* b0 = (const float*)d_in[2];
    const float* W1 = (const float*)d_in[3];
    const float* b1 = (const float*)d_in[4];
    const float* Wp = (const float*)d_in[5];
    const float* bp = (const float*)d_in[6];
    float* out = (float*)d_out;

    cudaFuncSetAttribute(lstm_main, cudaFuncAttributeMaxDynamicSharedMemorySize, 212992);

    prep_kernel<<<2048, 256>>>(x, W0, W1);
    lstm_main<<<NCTA, 256, 212992>>>(b0, b1, Wp, bp, out);
}

// round 15
// speedup vs baseline: 1.7342x; 1.7342x over previous
#include <cuda_runtime.h>
#include <cuda_fp16.h>

#define B_   128
#define S_   512
#define D_   256
#define H_   512
#define ODIM 1275
#define NCTA 128

typedef unsigned long long u64;
typedef unsigned int u32;

// ---------------- persistent device scratch (pre-swizzled f16 tiles) ----------
// act tile = [128 rows][128 k] f16, 256B rows; 16B chunk c of row r at pos c^(r&7).
__device__ __align__(256) unsigned char g_xs[S_][2][32768];    // x: [t][ch]
__device__ __align__(256) unsigned char g_h0s[2][4][32768];    // h0: [buf][ch]
__device__ __align__(256) unsigned char g_h1s[2][4][32768];
__device__ __align__(256) unsigned char g_W0s[64][6][8192];    // [jt][ch] 32n x 128k
__device__ __align__(256) unsigned char g_W1s[64][8][8192];
__device__ unsigned g_flags[NCTA * 32];

// ---------------- helpers ----------------
__device__ __forceinline__ u32 smem_u32(const void* p) {
    u32 a; asm("{ .reg .u64 t; cvta.to.shared.u64 t, %1; cvt.u32.u64 %0, t; }" : "=r"(a) : "l"(p));
    return a;
}
__device__ __forceinline__ float ex2f(float x) { float y; asm("ex2.approx.ftz.f32 %0, %1;" : "=f"(y) : "f"(x)); return y; }
__device__ __forceinline__ float rcpf(float x) { float y; asm("rcp.approx.ftz.f32 %0, %1;" : "=f"(y) : "f"(x)); return y; }
__device__ __forceinline__ float fsig(float z)  { return rcpf(1.f + ex2f(-1.44269504088896f * z)); }
__device__ __forceinline__ float ftanh(float z) { return 1.f - 2.f * rcpf(1.f + ex2f(2.88539008177793f * z)); }

__device__ __forceinline__ void cp16(void* dst, const void* src) {
    u32 d = smem_u32(dst);
    asm volatile("cp.async.cg.shared.global [%0], [%1], 16;\n" :: "r"(d), "l"(src));
}
__device__ __forceinline__ void cp_commit() { asm volatile("cp.async.commit_group;\n" ::); }
#define CP_WAIT0() asm volatile("cp.async.wait_group 0;\n" ::)
#define CP_WAIT1() asm volatile("cp.async.wait_group 1;\n" ::)

#define LDM4(r0, r1, r2, r3, addr) \
    asm volatile("ldmatrix.sync.aligned.m8n8.x4.shared.b16 {%0,%1,%2,%3}, [%4];" \
        : "=r"(r0), "=r"(r1), "=r"(r2), "=r"(r3) : "r"(addr))

#define LDM2(r0, r1, addr) \
    asm volatile("ldmatrix.sync.aligned.m8n8.x2.shared.b16 {%0,%1}, [%2];" \
        : "=r"(r0), "=r"(r1) : "r"(addr))

#define MMA4(d, A0, A1, A2, A3, B0, B1) \
    asm volatile("mma.sync.aligned.m16n8k16.row.col.f32.f16.f16.f32 " \
        "{%0,%1,%2,%3}, {%4,%5,%6,%7}, {%8,%9}, {%0,%1,%2,%3};" \
        : "+f"((d)[0]), "+f"((d)[1]), "+f"((d)[2]), "+f"((d)[3]) \
        : "r"(A0), "r"(A1), "r"(A2), "r"(A3), "r"(B0), "r"(B1))

// ---------------- grid-wide barrier (per-CTA flag slots) ----------------
__device__ __forceinline__ void grid_sync_flag(int cta, int tid, unsigned gen) {
    __syncthreads();
    if (tid == 0) {
        __threadfence();
        *((volatile unsigned*)&g_flags[cta * 32]) = gen;
    }
    if (tid < NCTA) {
        while (*((volatile unsigned*)&g_flags[tid * 32]) < gen) { }
    }
    __threadfence();
    __syncthreads();
}

// swizzled element offset inside a [rows][128k] f16 tile
__device__ __forceinline__ u32 swzoff(int row, int k) {
    return (u32)row * 256u + ((((u32)(k >> 3)) ^ ((u32)row & 7u)) << 4) + (((u32)k & 7u) << 1);
}

// ---------------- prep: f16-convert + swizzle x, W; zero h ----------------
__global__ void prep_kernel(const float* __restrict__ x,
                            const float* __restrict__ W0,
                            const float* __restrict__ W1)
{
    const int stride = gridDim.x * blockDim.x;
    const int t0 = blockIdx.x * blockDim.x + threadIdx.x;

    if (t0 < NCTA * 32) g_flags[t0] = 0u;

    for (int i = t0; i < 2 * 4 * 32768 / 4; i += stride) {
        ((u32*)g_h0s)[i] = 0u;
        ((u32*)g_h1s)[i] = 0u;
    }
    for (int idx = t0; idx < S_ * 2 * 128 * 128; idx += stride) {
        int t   = idx / (2 * 128 * 128);
        int rem = idx % (2 * 128 * 128);
        int ch  = rem / (128 * 128);
        int b   = (rem / 128) % 128;
        int k   = rem % 128;
        float v = x[(b * S_ + t) * D_ + ch * 128 + k];
        *(__half*)(&g_xs[t][ch][swzoff(b, k)]) = __float2half_rn(v);
    }
    for (int idx = t0; idx < 64 * 6 * 32 * 128; idx += stride) {
        int jt  = idx / (6 * 32 * 128);
        int rem = idx % (6 * 32 * 128);
        int ch  = rem / (32 * 128);
        int n   = (rem / 128) % 32;
        int k   = rem % 128;
        float v = W0[(ch * 128 + k) * 2048 + (n >> 3) * 512 + jt * 8 + (n & 7)];
        *(__half*)(&g_W0s[jt][ch][swzoff(n, k)]) = __float2half_rn(v);
    }
    for (int idx = t0; idx < 64 * 8 * 32 * 128; idx += stride) {
        int jt  = idx / (8 * 32 * 128);
        int rem = idx % (8 * 32 * 128);
        int ch  = rem / (32 * 128);
        int n   = (rem / 128) % 32;
        int k   = rem % 128;
        float v = W1[(ch * 128 + k) * 2048 + (n >> 3) * 512 + jt * 8 + (n & 7)];
        *(__half*)(&g_W1s[jt][ch][swzoff(n, k)]) = __float2half_rn(v);
    }
}

// ---------------- linear 16KB stage (batch-half of a 32KB tile) ----------------
__device__ __forceinline__ void stage(unsigned char* dst, const unsigned char* src, int tid) {
    #pragma unroll
    for (int i = 0; i < 4; i++) {
        int o = (tid + (i << 8)) << 4;
        cp16(dst + o, src + o);
    }
}

// ---------------- per-lane ldmatrix/mma context ----------------
struct LaneCtx { u32 sA, rA, kgA, rB, kgB; };

// one K=128 chunk of D[M=32 cols][N=64 b]; per-warp m32 x n8.
// acc[mi*4 + {0..3}]: mi0 = gates i,f; mi1 = gates g,o (unit = lane>>2).
__device__ __forceinline__ void mma_chunk(u32 ab, u32 wb, float* acc, const LaneCtx& L) {
    const u32 aB0 = wb + L.rA * 256u;
    const u32 aB1 = aB0 + 4096u;              // +16 weight rows
    const u32 bB  = ab + L.rB * 256u;
    #pragma unroll
    for (int j = 0; j < 8; j++) {
        u32 kiA = ((((u32)(2 * j)) | L.kgA) ^ L.sA) << 4;
        u32 kiB = ((((u32)(2 * j)) | L.kgB) ^ (L.rB & 7u)) << 4;
        u32 a0, a1, a2, a3, e0, e1, e2, e3, b0, b1;
        LDM4(a0, a1, a2, a3, aB0 + kiA);
        LDM4(e0, e1, e2, e3, aB1 + kiA);
        LDM2(b0, b1, bB + kiB);
        MMA4(acc + 0, a0, a1, a2, a3, b0, b1);
        MMA4(acc + 4, e0, e1, e2, e3, b0, b1);
    }
}

// ---------------- GEMM phase: depth-2 staged ring over nq chunks ----------
__device__ __forceinline__ void gemm_phase(
    const unsigned char* q0, const unsigned char* q1, const unsigned char* q2,
    const unsigned char* q3, const unsigned char* q4, const unsigned char* q5,
    const unsigned char* q6, const unsigned char* q7, int nq,
    u32 wb, unsigned char* s_act, u32 actbase,
    float* acc, int tid, const LaneCtx& L)
{
    const unsigned char* q[8] = {q0, q1, q2, q3, q4, q5, q6, q7};
    #pragma unroll
    for (int i = 0; i < 8; i++) acc[i] = 0.f;

    stage(s_act, q[0], tid); cp_commit();
    stage(s_act + 16384, q[1], tid); cp_commit();

    int buf = 0;
    for (int g = 0; g < nq; g++) {
        if (g < nq - 1) { CP_WAIT1(); } else { CP_WAIT0(); }
        __syncthreads();
        if (g + 2 < nq) {
            int nb = buf + 2; if (nb >= 3) nb -= 3;
            stage(s_act + nb * 16384, q[g + 2], tid);
            cp_commit();
        }
        mma_chunk(actbase + (u32)buf * 16384u, wb + ((u32)g << 13), acc, L);
        if (++buf == 3) buf = 0;
    }
    __syncthreads();
}

// ---------------- epilogue: in-register gates, f16 h store ----------------
__device__ __forceinline__ void epilogue(
    const float* acc, float* cst, float4 bias,
    unsigned char* hdst, u32 cj, int lane, int warp, int u, int bh)
{
    #pragma unroll
    for (int e = 0; e < 2; e++) {
        float zi = acc[e]     + bias.x;
        float zf = acc[2 + e] + bias.y;
        float zg = acc[4 + e] + bias.z;
        float zo = acc[6 + e] + bias.w;
        float c  = cst[e];
        float cn = fsig(zf) * c + fsig(zi) * ftanh(zg);
        cst[e] = cn;
        float h = fsig(zo) * ftanh(cn);
        int b = bh * 64 + warp * 8 + (lane & 3) * 2 + e;
        u32 off = (u32)b * 256u + ((cj ^ ((u32)b & 7u)) << 4) + (u32)u * 2u;
        *(__half*)(hdst + off) = __float2half_rn(h);
    }
}

// ---------------- persistent main kernel: 128 CTAs x 256 threads ----------------
__global__ void __launch_bounds__(256, 1)
lstm_main(const float* __restrict__ b0g,
          const float* __restrict__ b1g,
          const float* __restrict__ Wp,
          const float* __restrict__ bp,
          float* __restrict__ out)
{
    extern __shared__ __align__(256) unsigned char smem[];
    unsigned char* s_w   = smem;             // 6*8192 + 8*8192 = 114688
    unsigned char* s_act = smem + 114688;    // 3 x 16384 = 49152 -> total 163840

    const int tid  = threadIdx.x;
    const int lane = tid & 31;
    const int warp = tid >> 5;
    const int cta  = blockIdx.x;
    const int jt   = cta >> 1;               // col tile (32 cols)
    const int bh   = cta & 1;                // batch half (64 batches)
    const int u    = lane >> 2;              // unit 0..7 within CTA

    // preload weights (f16, pre-swizzled): 48KB + 64KB, linear cp.async
    {
        const unsigned char* w0 = &g_W0s[jt][0][0];
        const unsigned char* w1 = &g_W1s[jt][0][0];
        #pragma unroll
        for (int i = 0; i < 12; i++) { int o = (tid + (i << 8)) << 4; cp16(s_w + o, w0 + o); }
        #pragma unroll
        for (int i = 0; i < 16; i++) { int o = (tid + (i << 8)) << 4; cp16(s_w + 49152 + o, w1 + o); }
        cp_commit();
        CP_WAIT0();
    }
    __syncthreads();

    const int jb = jt * 8 + u;
    const float4 bias0 = make_float4(b0g[jb], b0g[512 + jb], b0g[1024 + jb], b0g[1536 + jb]);
    const float4 bias1 = make_float4(b1g[jb], b1g[512 + jb], b1g[1024 + jb], b1g[1536 + jb]);

    float c0r[2] = {0.f, 0.f};
    float c1r[2] = {0.f, 0.f};
    float acc[8];

    const u32 actbase = smem_u32(s_act);
    const u32 wb0 = smem_u32(s_w);
    const u32 wb1 = wb0 + 49152u;
    const u32 cj = (u32)((jt * 8) & 127) >> 3;
    const int htile = (jt * 8) >> 7;
    const u32 boff = (u32)bh << 14;          // 16KB: batch-half byte offset in act tiles

    LaneCtx L;
    L.sA  = (u32)(lane & 7);
    L.rA  = (u32)((((lane >> 3) & 1) << 3) | (lane & 7));
    L.kgA = (u32)(lane >> 4);
    L.rB  = (u32)((lane & 7) + warp * 8);    // local batch row within 64-row half
    L.kgB = (u32)((lane >> 3) & 1);

    for (int t = 0; t < S_; t++) {
        const int cur = t & 1, prv = cur ^ 1;

        // ---- L0: K = 768 = [x 2 chunks][h0_prev 4 chunks], batch-half slices ----
        gemm_phase(&g_xs[t][0][boff], &g_xs[t][1][boff],
                   &g_h0s[prv][0][boff], &g_h0s[prv][1][boff],
                   &g_h0s[prv][2][boff], &g_h0s[prv][3][boff], 0, 0, 6,
                   wb0, s_act, actbase, acc, tid, L);
        epilogue(acc, c0r, bias0, &g_h0s[cur][htile][0], cj, lane, warp, u, bh);

        grid_sync_flag(cta, tid, (unsigned)(t + 1));   // h0(t), h1(t-1) final everywhere

        // ---- L1: K = 1024 = [h0_cur 4][h1_prev 4] ----
        gemm_phase(&g_h0s[cur][0][boff], &g_h0s[cur][1][boff],
                   &g_h0s[cur][2][boff], &g_h0s[cur][3][boff],
                   &g_h1s[prv][0][boff], &g_h1s[prv][1][boff],
                   &g_h1s[prv][2][boff], &g_h1s[prv][3][boff], 8,
                   wb1, s_act, actbase, acc, tid, L);
        epilogue(acc, c1r, bias1, &g_h1s[cur][htile][0], cj, lane, warp, u, bh);
        // next step's barrier orders h1(t) -> L1(t+1)
    }

    grid_sync_flag(cta, tid, (unsigned)(S_ + 1));

    // ---- projection: out[b][m] = sum_j h1[b][j] * Wp[j][m] + bp[m] ----
    {
        const unsigned char* h1b = &g_h1s[1][0][0];   // buf 1 (t = 511)
        int mstart = cta * 10;
        int mend = mstart + 10; if (mend > ODIM) mend = ODIM;
        int b  = tid & 127;
        int mq = tid >> 7;     // 0..1
        for (int m = mstart + mq; m < mend; m += 2) {
            float a = bp[m];
            for (int k = 0; k < H_; k++) {
                u32 off = swzoff(b, k & 127);
                a += __half2float(*(const __half*)(h1b + (size_t)(k >> 7) * 32768 + off))
                     * Wp[k * ODIM + m];
            }
            out[b * ODIM + m] = a;
        }
    }
}

// ---------------- entry ----------------
extern "C" void kernel_launch(void* const* d_in, const int* in_sizes, int n_in,
                              void* d_out, int out_size)
{
    const float* x  = (const float*)d_in[0];
    const float* W0 = (const float*)d_in[1];
    const float* b0 = (const float*)d_in[2];
    const float* W1 = (const float*)d_in[3];
    const float* b1 = (const float*)d_in[4];
    const float* Wp = (const float*)d_in[5];
    const float* bp = (const float*)d_in[6];
    float* out = (float*)d_out;

    cudaFuncSetAttribute(lstm_main, cudaFuncAttributeMaxDynamicSharedMemorySize, 163840);

    prep_kernel<<<2048, 256>>>(x, W0, W1);
    lstm_main<<<NCTA, 256, 163840>>>(b0, b1, Wp, bp, out);
}